// round 12
// baseline (speedup 1.0000x reference)
#include <cuda_runtime.h>
#include <cuda_bf16.h>
#include <math.h>
#include <stdint.h>

// Problem constants
#define BATCH   32
#define HRES    64
#define WRES    64
#define DIM     192
#define C3      576
#define HID     768
#define NHEAD   6
#define HD      32
#define MTOK    (BATCH * HRES * WRES)   // 131072 rows
#define NWIN    (MTOK / 64)             // 2048 windows
#define QSCALE  0.17677669529663687f    // 1/sqrt(32)

// ---------------- static scratch (allocation-free rule) ----------------
__device__ __align__(256) float g_ln  [(size_t)MTOK * DIM];
__device__ __align__(256) float g_qkv [(size_t)MTOK * C3];
__device__ __align__(256) float g_attn[(size_t)MTOK * DIM];
__device__ __align__(256) float g_x2  [(size_t)MTOK * DIM];
__device__ __align__(256) float g_mlp [(size_t)MTOK * HID];

__device__ __forceinline__ int orig_row(int wr) {
    int b  = wr >> 12;
    int r  = wr & 4095;
    int wb = r >> 6;
    int n  = r & 63;
    int hh = ((wb >> 3) << 3) + (n >> 3);
    int ww = ((wb & 7) << 3) + (n & 7);
    return (b << 12) + (hh << 6) + ww;
}

// Feed raw fp32 bits to the tf32 MMA (HW reads top 19 bits; truncation).
__device__ __forceinline__ void mma_tf32(float c[4], const uint32_t a[4], const uint32_t b[2]) {
    asm volatile(
        "mma.sync.aligned.m16n8k8.row.col.f32.tf32.tf32.f32 "
        "{%0,%1,%2,%3}, {%4,%5,%6,%7}, {%8,%9}, {%0,%1,%2,%3};"
        : "+f"(c[0]), "+f"(c[1]), "+f"(c[2]), "+f"(c[3])
        : "r"(a[0]), "r"(a[1]), "r"(a[2]), "r"(a[3]), "r"(b[0]), "r"(b[1]));
}

#define CP16(dst_u32, src_ptr) \
    asm volatile("cp.async.cg.shared.global [%0], [%1], 16;" :: "r"(dst_u32), "l"(src_ptr))
#define CP_COMMIT() asm volatile("cp.async.commit_group;")
#define CP_WAIT(n)  asm volatile("cp.async.wait_group %0;" :: "n"(n))

// ---------------- LayerNorm: one warp per row of 192 ----------------
template<bool FROM_X2>
__global__ void ln_kernel(const float* __restrict__ xin,
                          const float* __restrict__ gamma,
                          const float* __restrict__ beta) {
    int warp = (blockIdx.x * blockDim.x + threadIdx.x) >> 5;
    int lane = threadIdx.x & 31;
    if (warp >= MTOK) return;
    const float* src = FROM_X2 ? g_x2 : xin;
    const float* row = src + (size_t)warp * DIM;
    float v[6];
    float s = 0.f, s2 = 0.f;
#pragma unroll
    for (int i = 0; i < 6; i++) {
        v[i] = row[lane + i * 32];
        s  += v[i];
        s2 += v[i] * v[i];
    }
#pragma unroll
    for (int off = 16; off > 0; off >>= 1) {
        s  += __shfl_xor_sync(0xffffffff, s,  off);
        s2 += __shfl_xor_sync(0xffffffff, s2, off);
    }
    float mean = s * (1.0f / DIM);
    float var  = s2 * (1.0f / DIM) - mean * mean;
    float rs   = rsqrtf(var + 1e-5f);
    float* dst = g_ln + (size_t)warp * DIM;
#pragma unroll
    for (int i = 0; i < 6; i++) {
        int c = lane + i * 32;
        dst[c] = (v[i] - mean) * rs * gamma[c] + beta[c];
    }
}

// ---------------- TF32 TC GEMM, 128x64x32, 4-stage cp.async pipeline -----
// Lookahead 2 slabs, wait_group(2), ONE __syncthreads per slab.
#define AS_STRIDE 36
#define BS_STRIDE 72
#define ABUF_F    (128 * AS_STRIDE)            // 4608
#define BBUF_F    (32 * BS_STRIDE)             // 2304
#define STAGE_F   (ABUF_F + BBUF_F)            // 6912 words per stage
#define NSTAGE    4

template<int MODE, int K, int N>
__global__ __launch_bounds__(256)
void gemm_tc(const float* __restrict__ Bw,
             const float* __restrict__ bias,
             const float* __restrict__ extra,
             float* __restrict__ outp) {
    const float* A;
    if (MODE == 0 || MODE == 2) A = g_ln;
    else if (MODE == 1)          A = g_attn;
    else                         A = g_mlp;

    __shared__ __align__(16) uint32_t smem[NSTAGE * STAGE_F];

    int tid   = threadIdx.x;
    int lane  = tid & 31;
    int warp  = tid >> 5;
    int warpM = warp >> 1;
    int warpN = warp & 1;
    int rowBase = blockIdx.y << 7;
    int colBase = blockIdx.x << 6;

    int aR  = tid >> 3;                // 0..31 (+32i)
    int aC4 = (tid & 7) << 2;          // 0,4..28
    int bK  = tid >> 4;                // 0..15 (+16i)
    int bN4 = (tid & 15) << 2;         // 0..60

    const float* aSrc[4];
#pragma unroll
    for (int i = 0; i < 4; i++) {
        int r = rowBase + aR + i * 32;
        int g = (MODE == 0) ? orig_row(r) : r;
        aSrc[i] = A + (size_t)g * K + aC4;
    }
    const float* bSrc = Bw + (size_t)bK * N + colBase + bN4;

    uint32_t sBase = (uint32_t)__cvta_generic_to_shared(smem);
    uint32_t aDst[4], bDst[2];
#pragma unroll
    for (int i = 0; i < 4; i++)
        aDst[i] = sBase + ((aR + i * 32) * AS_STRIDE + aC4) * 4;
#pragma unroll
    for (int i = 0; i < 2; i++)
        bDst[i] = sBase + (ABUF_F + (bK + i * 16) * BS_STRIDE + bN4) * 4;

    const int NT = K / 32;
    float acc[2][4][4] = {};

    // prologue: issue stages 0 and 1 as separate groups
#pragma unroll
    for (int s = 0; s < 2; s++) {
        uint32_t off = s * STAGE_F * 4;
        int kt = s * 32;
#pragma unroll
        for (int i = 0; i < 4; i++) CP16(aDst[i] + off, aSrc[i] + kt);
#pragma unroll
        for (int i = 0; i < 2; i++) CP16(bDst[i] + off, bSrc + (size_t)(kt + i * 16) * N);
        CP_COMMIT();
    }

    int ar = (warpM << 5) + (lane >> 2);
    int bn = (warpN << 5) + (lane >> 2);

    for (int t = 0; t < NT; t++) {
        // issue stage t+2 (buffer (t+2)%4 — safe: its last readers finished
        // one barrier ago); commit every iteration to keep wait-count uniform
        if (t + 2 < NT) {
            uint32_t off = ((t + 2) & 3) * STAGE_F * 4;
            int kt = (t + 2) * 32;
#pragma unroll
            for (int i = 0; i < 4; i++) CP16(aDst[i] + off, aSrc[i] + kt);
#pragma unroll
            for (int i = 0; i < 2; i++)
                CP16(bDst[i] + off, bSrc + (size_t)(kt + i * 16) * N);
        }
        CP_COMMIT();
        CP_WAIT(2);          // stage t complete
        __syncthreads();     // single barrier per slab

        const uint32_t* Ab = smem + (t & 3) * STAGE_F;
        const uint32_t* Bb = Ab + ABUF_F;
#pragma unroll
        for (int k8 = 0; k8 < 4; k8++) {
            uint32_t a[2][4], b[4][2];
            int ac = (k8 << 3) + (lane & 3);
#pragma unroll
            for (int mt = 0; mt < 2; mt++) {
                int r = ar + mt * 16;
                a[mt][0] = Ab[r * AS_STRIDE + ac];
                a[mt][1] = Ab[(r + 8) * AS_STRIDE + ac];
                a[mt][2] = Ab[r * AS_STRIDE + ac + 4];
                a[mt][3] = Ab[(r + 8) * AS_STRIDE + ac + 4];
            }
#pragma unroll
            for (int nt = 0; nt < 4; nt++) {
                b[nt][0] = Bb[ac * BS_STRIDE + bn + nt * 8];
                b[nt][1] = Bb[(ac + 4) * BS_STRIDE + bn + nt * 8];
            }
#pragma unroll
            for (int mt = 0; mt < 2; mt++)
#pragma unroll
                for (int nt = 0; nt < 4; nt++)
                    mma_tf32(acc[mt][nt], a[mt], b[nt]);
        }
    }

    // ---------------- epilogue ----------------
    int rBase = rowBase + (warpM << 5) + (lane >> 2);
    int cBase = colBase + (warpN << 5) + ((lane & 3) << 1);
#pragma unroll
    for (int mt = 0; mt < 2; mt++) {
#pragma unroll
        for (int half = 0; half < 2; half++) {
            int m = rBase + mt * 16 + half * 8;
            int om = m;
            if (MODE == 1) om = orig_row(m);
#pragma unroll
            for (int nt = 0; nt < 4; nt++) {
#pragma unroll
                for (int j = 0; j < 2; j++) {
                    int n = cBase + nt * 8 + j;
                    float v = acc[mt][nt][half * 2 + j] + bias[n];
                    if (MODE == 0) {
                        if (n < DIM) v *= QSCALE;
                        g_qkv[(size_t)m * C3 + n] = v;
                    } else if (MODE == 1) {
                        g_x2[(size_t)om * DIM + n] = extra[(size_t)om * DIM + n] + v;
                    } else if (MODE == 2) {
                        g_mlp[(size_t)m * HID + n] =
                            0.5f * v * (1.0f + erff(v * 0.70710678118654752f));
                    } else {
                        outp[(size_t)m * DIM + n] = v + g_x2[(size_t)m * DIM + n];
                    }
                }
            }
        }
    }
}

// ---------------- attention: one block per (window, head), float4 LDS ----
__global__ __launch_bounds__(64)
void attn_kernel() {
    __shared__ float sq[64 * 32];
    __shared__ float sk[64 * 32];
    __shared__ float sv[64 * 32];

    int win  = blockIdx.x / NHEAD;
    int head = blockIdx.x % NHEAD;
    int tid  = threadIdx.x;   // 0..63

    const float* base = g_qkv + (size_t)win * 64 * C3;
    int qoff = head * HD;
    int koff = DIM + head * HD;
    int voff = 2 * DIM + head * HD;

    for (int idx = tid; idx < 64 * 8; idx += 64) {
        int n = idx >> 3, d4 = (idx & 7) << 2;
        *(float4*)&sq[n * 32 + d4] = *(const float4*)&base[n * C3 + qoff + d4];
        *(float4*)&sk[n * 32 + d4] = *(const float4*)&base[n * C3 + koff + d4];
        *(float4*)&sv[n * 32 + d4] = *(const float4*)&base[n * C3 + voff + d4];
    }
    __syncthreads();

    float qr[32];
#pragma unroll
    for (int d4 = 0; d4 < 8; d4++) {
        float4 v = *(const float4*)&sq[tid * 32 + d4 * 4];
        qr[d4 * 4 + 0] = v.x; qr[d4 * 4 + 1] = v.y;
        qr[d4 * 4 + 2] = v.z; qr[d4 * 4 + 3] = v.w;
    }

    float s[64];
    float mx = -1e30f;
#pragma unroll
    for (int j = 0; j < 64; j++) {
        float acc = 0.f;
#pragma unroll
        for (int d4 = 0; d4 < 8; d4++) {
            float4 kv = *(const float4*)&sk[j * 32 + d4 * 4];
            acc = fmaf(qr[d4 * 4 + 0], kv.x, acc);
            acc = fmaf(qr[d4 * 4 + 1], kv.y, acc);
            acc = fmaf(qr[d4 * 4 + 2], kv.z, acc);
            acc = fmaf(qr[d4 * 4 + 3], kv.w, acc);
        }
        s[j] = acc;
        mx = fmaxf(mx, acc);
    }
    float sum = 0.f;
#pragma unroll
    for (int j = 0; j < 64; j++) {
        s[j] = __expf(s[j] - mx);
        sum += s[j];
    }
    float inv = 1.0f / sum;

    float o[32] = {};
#pragma unroll
    for (int j = 0; j < 64; j++) {
        float p = s[j];
#pragma unroll
        for (int d4 = 0; d4 < 8; d4++) {
            float4 vv = *(const float4*)&sv[j * 32 + d4 * 4];
            o[d4 * 4 + 0] = fmaf(p, vv.x, o[d4 * 4 + 0]);
            o[d4 * 4 + 1] = fmaf(p, vv.y, o[d4 * 4 + 1]);
            o[d4 * 4 + 2] = fmaf(p, vv.z, o[d4 * 4 + 2]);
            o[d4 * 4 + 3] = fmaf(p, vv.w, o[d4 * 4 + 3]);
        }
    }

    float* obase = g_attn + (size_t)win * 64 * DIM + (size_t)tid * DIM + head * HD;
#pragma unroll
    for (int d4 = 0; d4 < 8; d4++) {
        float4 v;
        v.x = o[d4 * 4 + 0] * inv; v.y = o[d4 * 4 + 1] * inv;
        v.z = o[d4 * 4 + 2] * inv; v.w = o[d4 * 4 + 3] * inv;
        *(float4*)&obase[d4 * 4] = v;
    }
}

// ---------------- launcher ----------------
extern "C" void kernel_launch(void* const* d_in, const int* in_sizes, int n_in,
                              void* d_out, int out_size) {
    const float* x       = (const float*)d_in[0];
    const float* norm1_g = (const float*)d_in[1];
    const float* norm1_b = (const float*)d_in[2];
    const float* qkv_w   = (const float*)d_in[3];
    const float* qkv_b   = (const float*)d_in[4];
    const float* proj_w  = (const float*)d_in[5];
    const float* proj_b  = (const float*)d_in[6];
    const float* norm2_g = (const float*)d_in[7];
    const float* norm2_b = (const float*)d_in[8];
    const float* fc1_w   = (const float*)d_in[9];
    const float* fc1_b   = (const float*)d_in[10];
    const float* fc2_w   = (const float*)d_in[11];
    const float* fc2_b   = (const float*)d_in[12];
    float* out = (float*)d_out;

    ln_kernel<false><<<MTOK / 8, 256>>>(x, norm1_g, norm1_b);
    gemm_tc<0, DIM, C3><<<dim3(C3 / 64, MTOK / 128), 256>>>(qkv_w, qkv_b, nullptr, nullptr);
    attn_kernel<<<NWIN * NHEAD, 64>>>();
    gemm_tc<1, DIM, DIM><<<dim3(DIM / 64, MTOK / 128), 256>>>(proj_w, proj_b, x, nullptr);
    ln_kernel<true><<<MTOK / 8, 256>>>(nullptr, norm2_g, norm2_b);
    gemm_tc<2, DIM, HID><<<dim3(HID / 64, MTOK / 128), 256>>>(fc1_w, fc1_b, nullptr, nullptr);
    gemm_tc<3, HID, DIM><<<dim3(DIM / 64, MTOK / 128), 256>>>(fc2_w, fc2_b, nullptr, out);
}

// round 14
// speedup vs baseline: 1.1202x; 1.1202x over previous
#include <cuda_runtime.h>
#include <cuda_bf16.h>
#include <math.h>
#include <stdint.h>

// Problem constants
#define BATCH   32
#define HRES    64
#define WRES    64
#define DIM     192
#define C3      576
#define HID     768
#define NHEAD   6
#define HD      32
#define MTOK    (BATCH * HRES * WRES)   // 131072 rows
#define NWIN    (MTOK / 64)             // 2048 windows
#define QSCALE  0.17677669529663687f    // 1/sqrt(32)

typedef __nv_bfloat16 bf16;

// ---------------- static scratch (allocation-free rule) ----------------
// Activations bf16 (storage only; math stays tf32/fp32). Trunk fp32.
__device__ __align__(256) bf16  g_ln  [(size_t)MTOK * DIM];
__device__ __align__(256) bf16  g_qkv [(size_t)MTOK * C3];
__device__ __align__(256) bf16  g_attn[(size_t)MTOK * DIM];
__device__ __align__(256) float g_x2  [(size_t)MTOK * DIM];
__device__ __align__(256) bf16  g_mlp [(size_t)MTOK * HID];

__device__ __forceinline__ int orig_row(int wr) {
    int b  = wr >> 12;
    int r  = wr & 4095;
    int wb = r >> 6;
    int n  = r & 63;
    int hh = ((wb >> 3) << 3) + (n >> 3);
    int ww = ((wb & 7) << 3) + (n & 7);
    return (b << 12) + (hh << 6) + ww;
}

// Raw fp32 bits into tf32 MMA (HW reads top 19 bits).
__device__ __forceinline__ void mma_tf32(float c[4], const uint32_t a[4], const uint32_t b[2]) {
    asm volatile(
        "mma.sync.aligned.m16n8k8.row.col.f32.tf32.tf32.f32 "
        "{%0,%1,%2,%3}, {%4,%5,%6,%7}, {%8,%9}, {%0,%1,%2,%3};"
        : "+f"(c[0]), "+f"(c[1]), "+f"(c[2]), "+f"(c[3])
        : "r"(a[0]), "r"(a[1]), "r"(a[2]), "r"(a[3]), "r"(b[0]), "r"(b[1]));
}

#define CP16(dst_u32, src_ptr) \
    asm volatile("cp.async.cg.shared.global [%0], [%1], 16;" :: "r"(dst_u32), "l"(src_ptr))
#define CP_COMMIT() asm volatile("cp.async.commit_group;")
#define CP_WAIT(n)  asm volatile("cp.async.wait_group %0;" :: "n"(n))

// 4 packed bf16 -> 4 fp32 bit patterns (bf16<<16 is exact)
__device__ __forceinline__ uint4 bf4_expand(uint2 w) {
    uint4 r;
    r.x = w.x << 16;  r.y = w.x & 0xFFFF0000u;
    r.z = w.y << 16;  r.w = w.y & 0xFFFF0000u;
    return r;
}
__device__ __forceinline__ float bfbits_lo(uint32_t w) { return __uint_as_float(w << 16); }
__device__ __forceinline__ float bfbits_hi(uint32_t w) { return __uint_as_float(w & 0xFFFF0000u); }
__device__ __forceinline__ uint32_t pack_bf2(float a, float b) {
    __nv_bfloat162 t = __floats2bfloat162_rn(a, b);
    return *(uint32_t*)&t;
}

// ---------------- LayerNorm: one warp per row of 192, bf16 out -----------
template<bool FROM_X2>
__global__ void ln_kernel(const float* __restrict__ xin,
                          const float* __restrict__ gamma,
                          const float* __restrict__ beta) {
    int warp = (blockIdx.x * blockDim.x + threadIdx.x) >> 5;
    int lane = threadIdx.x & 31;
    if (warp >= MTOK) return;
    const float* src = FROM_X2 ? g_x2 : xin;
    const float* row = src + (size_t)warp * DIM;
    float v[6];
    float s = 0.f, s2 = 0.f;
#pragma unroll
    for (int i = 0; i < 6; i++) {
        v[i] = row[lane + i * 32];
        s  += v[i];
        s2 += v[i] * v[i];
    }
#pragma unroll
    for (int off = 16; off > 0; off >>= 1) {
        s  += __shfl_xor_sync(0xffffffff, s,  off);
        s2 += __shfl_xor_sync(0xffffffff, s2, off);
    }
    float mean = s * (1.0f / DIM);
    float var  = s2 * (1.0f / DIM) - mean * mean;
    float rs   = rsqrtf(var + 1e-5f);
    bf16* dst = g_ln + (size_t)warp * DIM;
#pragma unroll
    for (int i = 0; i < 6; i++) {
        int c = lane + i * 32;
        dst[c] = __float2bfloat16((v[i] - mean) * rs * gamma[c] + beta[c]);
    }
}

// ---------------- TF32 TC GEMM, 128x64x32 ---------------------------------
// A: bf16 in gmem, register-pipelined LDG.64 -> expand -> STS.128 (fp32 smem).
// B: fp32 weights via cp.async. Mainloop identical to R9 (pure LDS + HMMA).
#define AS_STRIDE 36
#define BS_STRIDE 72
#define ABUF_F    (128 * AS_STRIDE)            // 4608
#define BBUF_F    (32 * BS_STRIDE)             // 2304
#define STAGE_F   (ABUF_F + BBUF_F)            // 6912 words per stage

template<int MODE, int K, int N>
__global__ __launch_bounds__(256)
void gemm_tc(const float* __restrict__ Bw,
             const float* __restrict__ bias,
             const float* __restrict__ extra,
             float* __restrict__ outp) {
    const bf16* A;
    if (MODE == 0 || MODE == 2) A = g_ln;
    else if (MODE == 1)          A = g_attn;
    else                         A = g_mlp;

    __shared__ __align__(16) uint32_t smem[2 * STAGE_F];

    int tid   = threadIdx.x;
    int lane  = tid & 31;
    int warp  = tid >> 5;
    int warpM = warp >> 1;
    int warpN = warp & 1;
    int rowBase = blockIdx.y << 7;
    int colBase = blockIdx.x << 6;

    int aR  = tid >> 3;                // 0..31 (+32i)
    int aC4 = (tid & 7) << 2;          // 0,4..28 (elements)
    int bK  = tid >> 4;                // 0..15 (+16i)
    int bN4 = (tid & 15) << 2;         // 0..60

    const bf16* aSrc[4];
#pragma unroll
    for (int i = 0; i < 4; i++) {
        int r = rowBase + aR + i * 32;
        int g = (MODE == 0) ? orig_row(r) : r;
        aSrc[i] = A + (size_t)g * K + aC4;
    }
    const float* bSrc = Bw + (size_t)bK * N + colBase + bN4;

    uint32_t sBase = (uint32_t)__cvta_generic_to_shared(smem);
    uint32_t* aSt[4];
#pragma unroll
    for (int i = 0; i < 4; i++)
        aSt[i] = smem + (aR + i * 32) * AS_STRIDE + aC4;
    uint32_t bDst[2];
#pragma unroll
    for (int i = 0; i < 2; i++)
        bDst[i] = sBase + (ABUF_F + (bK + i * 16) * BS_STRIDE + bN4) * 4;

    const int NT = K / 32;
    float acc[2][4][4] = {};
    uint2 aw[4];

    // prologue: stage 0 — A manual, B cp.async
#pragma unroll
    for (int i = 0; i < 4; i++) aw[i] = *(const uint2*)(aSrc[i]);
#pragma unroll
    for (int i = 0; i < 4; i++) *(uint4*)aSt[i] = bf4_expand(aw[i]);
#pragma unroll
    for (int i = 0; i < 2; i++) CP16(bDst[i], bSrc + (size_t)(i * 16) * N);
    CP_COMMIT();

    int ar = (warpM << 5) + (lane >> 2);
    int bn = (warpN << 5) + (lane >> 2);

    for (int t = 0; t < NT; t++) {
        int buf = t & 1;
        if (t + 1 < NT) {
            int kt = (t + 1) * 32;
#pragma unroll
            for (int i = 0; i < 4; i++) aw[i] = *(const uint2*)(aSrc[i] + kt);
            uint32_t off = (buf ^ 1) * STAGE_F * 4;
#pragma unroll
            for (int i = 0; i < 2; i++)
                CP16(bDst[i] + off, bSrc + (size_t)(kt + i * 16) * N);
            CP_COMMIT();
            CP_WAIT(1);
        } else {
            CP_WAIT(0);
        }
        __syncthreads();

        const uint32_t* Ab = smem + buf * STAGE_F;
        const uint32_t* Bb = Ab + ABUF_F;
#pragma unroll
        for (int k8 = 0; k8 < 4; k8++) {
            uint32_t a[2][4], b[4][2];
            int ac = (k8 << 3) + (lane & 3);
#pragma unroll
            for (int mt = 0; mt < 2; mt++) {
                int r = ar + mt * 16;
                a[mt][0] = Ab[r * AS_STRIDE + ac];
                a[mt][1] = Ab[(r + 8) * AS_STRIDE + ac];
                a[mt][2] = Ab[r * AS_STRIDE + ac + 4];
                a[mt][3] = Ab[(r + 8) * AS_STRIDE + ac + 4];
            }
#pragma unroll
            for (int nt = 0; nt < 4; nt++) {
                b[nt][0] = Bb[ac * BS_STRIDE + bn + nt * 8];
                b[nt][1] = Bb[(ac + 4) * BS_STRIDE + bn + nt * 8];
            }
#pragma unroll
            for (int mt = 0; mt < 2; mt++)
#pragma unroll
                for (int nt = 0; nt < 4; nt++)
                    mma_tf32(acc[mt][nt], a[mt], b[nt]);
        }

        // stage next A slab into the other buffer (free since last barrier)
        if (t + 1 < NT) {
            uint32_t woff = (buf ^ 1) * STAGE_F;
#pragma unroll
            for (int i = 0; i < 4; i++) *(uint4*)(aSt[i] + woff) = bf4_expand(aw[i]);
        }
        __syncthreads();
    }

    // ---------------- epilogue ----------------
    int rBase = rowBase + (warpM << 5) + (lane >> 2);
    int cBase = colBase + (warpN << 5) + ((lane & 3) << 1);
#pragma unroll
    for (int mt = 0; mt < 2; mt++) {
#pragma unroll
        for (int half = 0; half < 2; half++) {
            int m = rBase + mt * 16 + half * 8;
            int om = m;
            if (MODE == 1) om = orig_row(m);
#pragma unroll
            for (int nt = 0; nt < 4; nt++) {
                int n0 = cBase + nt * 8;
                float v0 = acc[mt][nt][half * 2 + 0] + bias[n0];
                float v1 = acc[mt][nt][half * 2 + 1] + bias[n0 + 1];
                if (MODE == 0) {
                    if (n0 < DIM) { v0 *= QSCALE; v1 *= QSCALE; }
                    *(uint32_t*)&g_qkv[(size_t)m * C3 + n0] = pack_bf2(v0, v1);
                } else if (MODE == 1) {
                    g_x2[(size_t)om * DIM + n0]     = extra[(size_t)om * DIM + n0] + v0;
                    g_x2[(size_t)om * DIM + n0 + 1] = extra[(size_t)om * DIM + n0 + 1] + v1;
                } else if (MODE == 2) {
                    float g0 = 0.5f * v0 * (1.0f + erff(v0 * 0.70710678118654752f));
                    float g1 = 0.5f * v1 * (1.0f + erff(v1 * 0.70710678118654752f));
                    *(uint32_t*)&g_mlp[(size_t)m * HID + n0] = pack_bf2(g0, g1);
                } else {
                    outp[(size_t)m * DIM + n0]     = v0 + g_x2[(size_t)m * DIM + n0];
                    outp[(size_t)m * DIM + n0 + 1] = v1 + g_x2[(size_t)m * DIM + n0 + 1];
                }
            }
        }
    }
}

// ---------------- attention: one block per (window, head) ----------------
// g_qkv is bf16; convert to fp32 smem tiles at staging.
__global__ __launch_bounds__(64)
void attn_kernel() {
    __shared__ float sq[64 * 32];
    __shared__ float sk[64 * 32];
    __shared__ float sv[64 * 32];

    int win  = blockIdx.x / NHEAD;
    int head = blockIdx.x % NHEAD;
    int tid  = threadIdx.x;   // 0..63

    const bf16* base = g_qkv + (size_t)win * 64 * C3;
    int qoff = head * HD;
    int koff = DIM + head * HD;
    int voff = 2 * DIM + head * HD;

    for (int idx = tid; idx < 64 * 8; idx += 64) {
        int n = idx >> 3, d4 = (idx & 7) << 2;
        uint2 wq = *(const uint2*)&base[n * C3 + qoff + d4];
        uint2 wk = *(const uint2*)&base[n * C3 + koff + d4];
        uint2 wv = *(const uint2*)&base[n * C3 + voff + d4];
        float4 fq = { bfbits_lo(wq.x), bfbits_hi(wq.x), bfbits_lo(wq.y), bfbits_hi(wq.y) };
        float4 fk = { bfbits_lo(wk.x), bfbits_hi(wk.x), bfbits_lo(wk.y), bfbits_hi(wk.y) };
        float4 fv = { bfbits_lo(wv.x), bfbits_hi(wv.x), bfbits_lo(wv.y), bfbits_hi(wv.y) };
        *(float4*)&sq[n * 32 + d4] = fq;
        *(float4*)&sk[n * 32 + d4] = fk;
        *(float4*)&sv[n * 32 + d4] = fv;
    }
    __syncthreads();

    float qr[32];
#pragma unroll
    for (int d4 = 0; d4 < 8; d4++) {
        float4 v = *(const float4*)&sq[tid * 32 + d4 * 4];
        qr[d4 * 4 + 0] = v.x; qr[d4 * 4 + 1] = v.y;
        qr[d4 * 4 + 2] = v.z; qr[d4 * 4 + 3] = v.w;
    }

    float s[64];
    float mx = -1e30f;
#pragma unroll
    for (int j = 0; j < 64; j++) {
        float acc = 0.f;
#pragma unroll
        for (int d4 = 0; d4 < 8; d4++) {
            float4 kv = *(const float4*)&sk[j * 32 + d4 * 4];
            acc = fmaf(qr[d4 * 4 + 0], kv.x, acc);
            acc = fmaf(qr[d4 * 4 + 1], kv.y, acc);
            acc = fmaf(qr[d4 * 4 + 2], kv.z, acc);
            acc = fmaf(qr[d4 * 4 + 3], kv.w, acc);
        }
        s[j] = acc;
        mx = fmaxf(mx, acc);
    }
    float sum = 0.f;
#pragma unroll
    for (int j = 0; j < 64; j++) {
        s[j] = __expf(s[j] - mx);
        sum += s[j];
    }
    float inv = 1.0f / sum;

    float o[32] = {};
#pragma unroll
    for (int j = 0; j < 64; j++) {
        float p = s[j];
#pragma unroll
        for (int d4 = 0; d4 < 8; d4++) {
            float4 vv = *(const float4*)&sv[j * 32 + d4 * 4];
            o[d4 * 4 + 0] = fmaf(p, vv.x, o[d4 * 4 + 0]);
            o[d4 * 4 + 1] = fmaf(p, vv.y, o[d4 * 4 + 1]);
            o[d4 * 4 + 2] = fmaf(p, vv.z, o[d4 * 4 + 2]);
            o[d4 * 4 + 3] = fmaf(p, vv.w, o[d4 * 4 + 3]);
        }
    }

    bf16* obase = g_attn + (size_t)win * 64 * DIM + (size_t)tid * DIM + head * HD;
#pragma unroll
    for (int d4 = 0; d4 < 8; d4++) {
        uint2 w;
        w.x = pack_bf2(o[d4 * 4 + 0] * inv, o[d4 * 4 + 1] * inv);
        w.y = pack_bf2(o[d4 * 4 + 2] * inv, o[d4 * 4 + 3] * inv);
        *(uint2*)&obase[d4 * 4] = w;
    }
}

// ---------------- launcher ----------------
extern "C" void kernel_launch(void* const* d_in, const int* in_sizes, int n_in,
                              void* d_out, int out_size) {
    const float* x       = (const float*)d_in[0];
    const float* norm1_g = (const float*)d_in[1];
    const float* norm1_b = (const float*)d_in[2];
    const float* qkv_w   = (const float*)d_in[3];
    const float* qkv_b   = (const float*)d_in[4];
    const float* proj_w  = (const float*)d_in[5];
    const float* proj_b  = (const float*)d_in[6];
    const float* norm2_g = (const float*)d_in[7];
    const float* norm2_b = (const float*)d_in[8];
    const float* fc1_w   = (const float*)d_in[9];
    const float* fc1_b   = (const float*)d_in[10];
    const float* fc2_w   = (const float*)d_in[11];
    const float* fc2_b   = (const float*)d_in[12];
    float* out = (float*)d_out;

    ln_kernel<false><<<MTOK / 8, 256>>>(x, norm1_g, norm1_b);
    gemm_tc<0, DIM, C3><<<dim3(C3 / 64, MTOK / 128), 256>>>(qkv_w, qkv_b, nullptr, nullptr);
    attn_kernel<<<NWIN * NHEAD, 64>>>();
    gemm_tc<1, DIM, DIM><<<dim3(DIM / 64, MTOK / 128), 256>>>(proj_w, proj_b, x, nullptr);
    ln_kernel<true><<<MTOK / 8, 256>>>(nullptr, norm2_g, norm2_b);
    gemm_tc<2, DIM, HID><<<dim3(HID / 64, MTOK / 128), 256>>>(fc1_w, fc1_b, nullptr, nullptr);
    gemm_tc<3, HID, DIM><<<dim3(DIM / 64, MTOK / 128), 256>>>(fc2_w, fc2_b, nullptr, out);
}

// round 16
// speedup vs baseline: 1.2866x; 1.1486x over previous
#include <cuda_runtime.h>
#include <cuda_bf16.h>
#include <math.h>
#include <stdint.h>

// Problem constants
#define BATCH   32
#define HRES    64
#define WRES    64
#define DIM     192
#define C3      576
#define HID     768
#define NHEAD   6
#define HD      32
#define MTOK    (BATCH * HRES * WRES)   // 131072 rows
#define NWIN    (MTOK / 64)             // 2048 windows
#define QSCALE  0.17677669529663687f    // 1/sqrt(32)

typedef __nv_bfloat16 bf16;

// ---------------- static scratch (allocation-free rule) ----------------
__device__ __align__(256) bf16  g_ln  [(size_t)MTOK * DIM];
__device__ __align__(256) bf16  g_qkv [(size_t)MTOK * C3];
__device__ __align__(256) bf16  g_attn[(size_t)MTOK * DIM];
__device__ __align__(256) float g_x2  [(size_t)MTOK * DIM];
__device__ __align__(256) bf16  g_mlp [(size_t)MTOK * HID];

__device__ __forceinline__ int orig_row(int wr) {
    int b  = wr >> 12;
    int r  = wr & 4095;
    int wb = r >> 6;
    int n  = r & 63;
    int hh = ((wb >> 3) << 3) + (n >> 3);
    int ww = ((wb & 7) << 3) + (n & 7);
    return (b << 12) + (hh << 6) + ww;
}

// Raw fp32 bits into tf32 MMA (HW reads top 19 bits).
__device__ __forceinline__ void mma_tf32(float c[4], const uint32_t a[4], const uint32_t b[2]) {
    asm volatile(
        "mma.sync.aligned.m16n8k8.row.col.f32.tf32.tf32.f32 "
        "{%0,%1,%2,%3}, {%4,%5,%6,%7}, {%8,%9}, {%0,%1,%2,%3};"
        : "+f"(c[0]), "+f"(c[1]), "+f"(c[2]), "+f"(c[3])
        : "r"(a[0]), "r"(a[1]), "r"(a[2]), "r"(a[3]), "r"(b[0]), "r"(b[1]));
}

#define CP16(dst_u32, src_ptr) \
    asm volatile("cp.async.cg.shared.global [%0], [%1], 16;" :: "r"(dst_u32), "l"(src_ptr))
#define CP_COMMIT() asm volatile("cp.async.commit_group;")
#define CP_WAIT(n)  asm volatile("cp.async.wait_group %0;" :: "n"(n))

// bf16 expand helpers (bf16<<16 is the exact fp32 bit pattern)
__device__ __forceinline__ uint4 bf4_expand(uint2 w) {
    uint4 r;
    r.x = w.x << 16;  r.y = w.x & 0xFFFF0000u;
    r.z = w.y << 16;  r.w = w.y & 0xFFFF0000u;
    return r;
}
__device__ __forceinline__ float bfbits_lo(uint32_t w) { return __uint_as_float(w << 16); }
__device__ __forceinline__ float bfbits_hi(uint32_t w) { return __uint_as_float(w & 0xFFFF0000u); }
__device__ __forceinline__ uint32_t pack_bf2(float a, float b) {
    __nv_bfloat162 t = __floats2bfloat162_rn(a, b);
    return *(uint32_t*)&t;
}

// ---------------- LayerNorm: one warp per row of 192, bf16 out -----------
template<bool FROM_X2>
__global__ void ln_kernel(const float* __restrict__ xin,
                          const float* __restrict__ gamma,
                          const float* __restrict__ beta) {
    int warp = (blockIdx.x * blockDim.x + threadIdx.x) >> 5;
    int lane = threadIdx.x & 31;
    if (warp >= MTOK) return;
    const float* src = FROM_X2 ? g_x2 : xin;
    const float* row = src + (size_t)warp * DIM;
    float v[6];
    float s = 0.f, s2 = 0.f;
#pragma unroll
    for (int i = 0; i < 6; i++) {
        v[i] = row[lane + i * 32];
        s  += v[i];
        s2 += v[i] * v[i];
    }
#pragma unroll
    for (int off = 16; off > 0; off >>= 1) {
        s  += __shfl_xor_sync(0xffffffff, s,  off);
        s2 += __shfl_xor_sync(0xffffffff, s2, off);
    }
    float mean = s * (1.0f / DIM);
    float var  = s2 * (1.0f / DIM) - mean * mean;
    float rs   = rsqrtf(var + 1e-5f);
    bf16* dst = g_ln + (size_t)warp * DIM;
#pragma unroll
    for (int i = 0; i < 6; i++) {
        int c = lane + i * 32;
        dst[c] = __float2bfloat16((v[i] - mean) * rs * gamma[c] + beta[c]);
    }
}

// ---------------- TF32 TC GEMM, 128x64x32 (proven R14 config) -------------
#define AS_STRIDE 36
#define BS_STRIDE 72
#define ABUF_F    (128 * AS_STRIDE)            // 4608
#define BBUF_F    (32 * BS_STRIDE)             // 2304
#define STAGE_F   (ABUF_F + BBUF_F)            // 6912 words per stage

template<int MODE, int K, int N>
__global__ __launch_bounds__(256)
void gemm_tc(const float* __restrict__ Bw,
             const float* __restrict__ bias,
             const float* __restrict__ extra,
             float* __restrict__ outp) {
    const bf16* A;
    if (MODE == 0 || MODE == 2) A = g_ln;
    else if (MODE == 1)          A = g_attn;
    else                         A = g_mlp;

    __shared__ __align__(16) uint32_t smem[2 * STAGE_F];

    int tid   = threadIdx.x;
    int lane  = tid & 31;
    int warp  = tid >> 5;
    int warpM = warp >> 1;
    int warpN = warp & 1;
    int rowBase = blockIdx.y << 7;
    int colBase = blockIdx.x << 6;

    int aR  = tid >> 3;                // 0..31 (+32i)
    int aC4 = (tid & 7) << 2;          // 0,4..28 (elements)
    int bK  = tid >> 4;                // 0..15 (+16i)
    int bN4 = (tid & 15) << 2;         // 0..60

    const bf16* aSrc[4];
#pragma unroll
    for (int i = 0; i < 4; i++) {
        int r = rowBase + aR + i * 32;
        int g = (MODE == 0) ? orig_row(r) : r;
        aSrc[i] = A + (size_t)g * K + aC4;
    }
    const float* bSrc = Bw + (size_t)bK * N + colBase + bN4;

    uint32_t sBase = (uint32_t)__cvta_generic_to_shared(smem);
    uint32_t* aSt[4];
#pragma unroll
    for (int i = 0; i < 4; i++)
        aSt[i] = smem + (aR + i * 32) * AS_STRIDE + aC4;
    uint32_t bDst[2];
#pragma unroll
    for (int i = 0; i < 2; i++)
        bDst[i] = sBase + (ABUF_F + (bK + i * 16) * BS_STRIDE + bN4) * 4;

    const int NT = K / 32;
    float acc[2][4][4] = {};
    uint2 aw[4];

    // prologue: stage 0 — A manual, B cp.async
#pragma unroll
    for (int i = 0; i < 4; i++) aw[i] = *(const uint2*)(aSrc[i]);
#pragma unroll
    for (int i = 0; i < 4; i++) *(uint4*)aSt[i] = bf4_expand(aw[i]);
#pragma unroll
    for (int i = 0; i < 2; i++) CP16(bDst[i], bSrc + (size_t)(i * 16) * N);
    CP_COMMIT();

    int ar = (warpM << 5) + (lane >> 2);
    int bn = (warpN << 5) + (lane >> 2);

    for (int t = 0; t < NT; t++) {
        int buf = t & 1;
        if (t + 1 < NT) {
            int kt = (t + 1) * 32;
#pragma unroll
            for (int i = 0; i < 4; i++) aw[i] = *(const uint2*)(aSrc[i] + kt);
            uint32_t off = (buf ^ 1) * STAGE_F * 4;
#pragma unroll
            for (int i = 0; i < 2; i++)
                CP16(bDst[i] + off, bSrc + (size_t)(kt + i * 16) * N);
            CP_COMMIT();
            CP_WAIT(1);
        } else {
            CP_WAIT(0);
        }
        __syncthreads();

        const uint32_t* Ab = smem + buf * STAGE_F;
        const uint32_t* Bb = Ab + ABUF_F;
#pragma unroll
        for (int k8 = 0; k8 < 4; k8++) {
            uint32_t a[2][4], b[4][2];
            int ac = (k8 << 3) + (lane & 3);
#pragma unroll
            for (int mt = 0; mt < 2; mt++) {
                int r = ar + mt * 16;
                a[mt][0] = Ab[r * AS_STRIDE + ac];
                a[mt][1] = Ab[(r + 8) * AS_STRIDE + ac];
                a[mt][2] = Ab[r * AS_STRIDE + ac + 4];
                a[mt][3] = Ab[(r + 8) * AS_STRIDE + ac + 4];
            }
#pragma unroll
            for (int nt = 0; nt < 4; nt++) {
                b[nt][0] = Bb[ac * BS_STRIDE + bn + nt * 8];
                b[nt][1] = Bb[(ac + 4) * BS_STRIDE + bn + nt * 8];
            }
#pragma unroll
            for (int mt = 0; mt < 2; mt++)
#pragma unroll
                for (int nt = 0; nt < 4; nt++)
                    mma_tf32(acc[mt][nt], a[mt], b[nt]);
        }

        // stage next A slab into the other buffer (free since last barrier)
        if (t + 1 < NT) {
            uint32_t woff = (buf ^ 1) * STAGE_F;
#pragma unroll
            for (int i = 0; i < 4; i++) *(uint4*)(aSt[i] + woff) = bf4_expand(aw[i]);
        }
        __syncthreads();
    }

    // ---------------- epilogue ----------------
    int rBase = rowBase + (warpM << 5) + (lane >> 2);
    int cBase = colBase + (warpN << 5) + ((lane & 3) << 1);
#pragma unroll
    for (int mt = 0; mt < 2; mt++) {
#pragma unroll
        for (int half = 0; half < 2; half++) {
            int m = rBase + mt * 16 + half * 8;
            int om = m;
            if (MODE == 1) om = orig_row(m);
#pragma unroll
            for (int nt = 0; nt < 4; nt++) {
                int n0 = cBase + nt * 8;
                float v0 = acc[mt][nt][half * 2 + 0] + bias[n0];
                float v1 = acc[mt][nt][half * 2 + 1] + bias[n0 + 1];
                if (MODE == 0) {
                    if (n0 < DIM) { v0 *= QSCALE; v1 *= QSCALE; }
                    *(uint32_t*)&g_qkv[(size_t)m * C3 + n0] = pack_bf2(v0, v1);
                } else if (MODE == 1) {
                    g_x2[(size_t)om * DIM + n0]     = extra[(size_t)om * DIM + n0] + v0;
                    g_x2[(size_t)om * DIM + n0 + 1] = extra[(size_t)om * DIM + n0 + 1] + v1;
                } else if (MODE == 2) {
                    float g0 = 0.5f * v0 * (1.0f + erff(v0 * 0.70710678118654752f));
                    float g1 = 0.5f * v1 * (1.0f + erff(v1 * 0.70710678118654752f));
                    *(uint32_t*)&g_mlp[(size_t)m * HID + n0] = pack_bf2(g0, g1);
                } else {
                    outp[(size_t)m * DIM + n0]     = v0 + g_x2[(size_t)m * DIM + n0];
                    outp[(size_t)m * DIM + n0 + 1] = v1 + g_x2[(size_t)m * DIM + n0 + 1];
                }
            }
        }
    }
}

// ---------------- attention: one block per WINDOW, tf32 MMA ---------------
// 128 threads = 4 warps; loop over 6 heads. Warp w owns query rows [16w,16w+16).
// QK^T and P@V via the proven m16n8k8 tf32 path; softmax on D-fragments with
// quad shuffles; P round-trips through per-warp-private smem rows.
__global__ __launch_bounds__(128)
void attn_kernel() {
    __shared__ float sq [64 * 36];   // q rows [tok][d]
    __shared__ float sk [64 * 36];   // k rows [tok][d]
    __shared__ float svt[32 * 69];   // v transposed [d][tok]
    __shared__ float sp [64 * 68];   // P (exp scores) [q][tok]

    int win  = blockIdx.x;
    int tid  = threadIdx.x;
    int lane = tid & 31;
    int warp = tid >> 5;          // 0..3
    int r4   = lane >> 2;         // 0..7
    int l4   = lane & 3;

    const bf16* base = g_qkv + (size_t)win * 64 * C3;
    int ar = warp * 16 + r4;      // this thread's base query row

    for (int h = 0; h < NHEAD; h++) {
        __syncthreads();          // protect restage vs previous head's reads
        int qoff = h * HD, koff = DIM + h * HD, voff = 2 * DIM + h * HD;
        for (int c = tid; c < 512; c += 128) {
            int tok = c >> 3, d4 = (c & 7) << 2;
            uint2 wq = *(const uint2*)&base[tok * C3 + qoff + d4];
            uint2 wk = *(const uint2*)&base[tok * C3 + koff + d4];
            uint2 wv = *(const uint2*)&base[tok * C3 + voff + d4];
            float4 fq = { bfbits_lo(wq.x), bfbits_hi(wq.x), bfbits_lo(wq.y), bfbits_hi(wq.y) };
            float4 fk = { bfbits_lo(wk.x), bfbits_hi(wk.x), bfbits_lo(wk.y), bfbits_hi(wk.y) };
            *(float4*)&sq[tok * 36 + d4] = fq;
            *(float4*)&sk[tok * 36 + d4] = fk;
            svt[(d4 + 0) * 69 + tok] = bfbits_lo(wv.x);
            svt[(d4 + 1) * 69 + tok] = bfbits_hi(wv.x);
            svt[(d4 + 2) * 69 + tok] = bfbits_lo(wv.y);
            svt[(d4 + 3) * 69 + tok] = bfbits_hi(wv.y);
        }
        __syncthreads();

        // ---- S = q @ k^T (64x64x32), warp tile 16x64 ----
        float s[8][4] = {};
#pragma unroll
        for (int k8 = 0; k8 < 4; k8++) {
            int ac = k8 * 8 + l4;
            uint32_t a[4];
            a[0] = __float_as_uint(sq[ar * 36 + ac]);
            a[1] = __float_as_uint(sq[(ar + 8) * 36 + ac]);
            a[2] = __float_as_uint(sq[ar * 36 + ac + 4]);
            a[3] = __float_as_uint(sq[(ar + 8) * 36 + ac + 4]);
#pragma unroll
            for (int nt = 0; nt < 8; nt++) {
                int bn = nt * 8 + r4;
                uint32_t bb[2] = { __float_as_uint(sk[bn * 36 + ac]),
                                   __float_as_uint(sk[bn * 36 + ac + 4]) };
                mma_tf32(s[nt], a, bb);
            }
        }

        // ---- softmax: rows ar (c0,c1) and ar+8 (c2,c3), quad-reduced ----
        float m0 = -1e30f, m1 = -1e30f;
#pragma unroll
        for (int nt = 0; nt < 8; nt++) {
            m0 = fmaxf(m0, fmaxf(s[nt][0], s[nt][1]));
            m1 = fmaxf(m1, fmaxf(s[nt][2], s[nt][3]));
        }
        m0 = fmaxf(m0, __shfl_xor_sync(0xffffffff, m0, 1));
        m0 = fmaxf(m0, __shfl_xor_sync(0xffffffff, m0, 2));
        m1 = fmaxf(m1, __shfl_xor_sync(0xffffffff, m1, 1));
        m1 = fmaxf(m1, __shfl_xor_sync(0xffffffff, m1, 2));
        float s0 = 0.f, s1 = 0.f;
#pragma unroll
        for (int nt = 0; nt < 8; nt++) {
            s[nt][0] = __expf(s[nt][0] - m0);
            s[nt][1] = __expf(s[nt][1] - m0);
            s[nt][2] = __expf(s[nt][2] - m1);
            s[nt][3] = __expf(s[nt][3] - m1);
            s0 += s[nt][0] + s[nt][1];
            s1 += s[nt][2] + s[nt][3];
        }
        s0 += __shfl_xor_sync(0xffffffff, s0, 1);
        s0 += __shfl_xor_sync(0xffffffff, s0, 2);
        s1 += __shfl_xor_sync(0xffffffff, s1, 1);
        s1 += __shfl_xor_sync(0xffffffff, s1, 2);
        float inv0 = 1.0f / s0, inv1 = 1.0f / s1;

        // ---- P to smem (warp-private rows; only syncwarp needed) ----
#pragma unroll
        for (int nt = 0; nt < 8; nt++) {
            int cc = nt * 8 + l4 * 2;
            *(float2*)&sp[ar * 68 + cc]       = make_float2(s[nt][0], s[nt][1]);
            *(float2*)&sp[(ar + 8) * 68 + cc] = make_float2(s[nt][2], s[nt][3]);
        }
        __syncwarp();

        // ---- O = P @ V (64x32x64), warp tile 16x32 ----
        float o[4][4] = {};
#pragma unroll
        for (int k8 = 0; k8 < 8; k8++) {
            int ac = k8 * 8 + l4;
            uint32_t a[4];
            a[0] = __float_as_uint(sp[ar * 68 + ac]);
            a[1] = __float_as_uint(sp[(ar + 8) * 68 + ac]);
            a[2] = __float_as_uint(sp[ar * 68 + ac + 4]);
            a[3] = __float_as_uint(sp[(ar + 8) * 68 + ac + 4]);
#pragma unroll
            for (int nt = 0; nt < 4; nt++) {
                int bn = nt * 8 + r4;
                uint32_t bb[2] = { __float_as_uint(svt[bn * 69 + ac]),
                                   __float_as_uint(svt[bn * 69 + ac + 4]) };
                mma_tf32(o[nt], a, bb);
            }
        }

        // ---- write O (normalized) bf16 ----
        size_t row0 = (size_t)(win * 64 + ar) * DIM;
        size_t row1 = row0 + 8 * DIM;
#pragma unroll
        for (int nt = 0; nt < 4; nt++) {
            int col = h * HD + nt * 8 + l4 * 2;
            *(uint32_t*)&g_attn[row0 + col] = pack_bf2(o[nt][0] * inv0, o[nt][1] * inv0);
            *(uint32_t*)&g_attn[row1 + col] = pack_bf2(o[nt][2] * inv1, o[nt][3] * inv1);
        }
    }
}

// ---------------- launcher ----------------
extern "C" void kernel_launch(void* const* d_in, const int* in_sizes, int n_in,
                              void* d_out, int out_size) {
    const float* x       = (const float*)d_in[0];
    const float* norm1_g = (const float*)d_in[1];
    const float* norm1_b = (const float*)d_in[2];
    const float* qkv_w   = (const float*)d_in[3];
    const float* qkv_b   = (const float*)d_in[4];
    const float* proj_w  = (const float*)d_in[5];
    const float* proj_b  = (const float*)d_in[6];
    const float* norm2_g = (const float*)d_in[7];
    const float* norm2_b = (const float*)d_in[8];
    const float* fc1_w   = (const float*)d_in[9];
    const float* fc1_b   = (const float*)d_in[10];
    const float* fc2_w   = (const float*)d_in[11];
    const float* fc2_b   = (const float*)d_in[12];
    float* out = (float*)d_out;

    ln_kernel<false><<<MTOK / 8, 256>>>(x, norm1_g, norm1_b);
    gemm_tc<0, DIM, C3><<<dim3(C3 / 64, MTOK / 128), 256>>>(qkv_w, qkv_b, nullptr, nullptr);
    attn_kernel<<<NWIN, 128>>>();
    gemm_tc<1, DIM, DIM><<<dim3(DIM / 64, MTOK / 128), 256>>>(proj_w, proj_b, x, nullptr);
    ln_kernel<true><<<MTOK / 8, 256>>>(nullptr, norm2_g, norm2_b);
    gemm_tc<2, DIM, HID><<<dim3(HID / 64, MTOK / 128), 256>>>(fc1_w, fc1_b, nullptr, nullptr);
    gemm_tc<3, HID, DIM><<<dim3(DIM / 64, MTOK / 128), 256>>>(fc2_w, fc2_b, nullptr, out);
}